// round 16
// baseline (speedup 1.0000x reference)
#include <cuda_runtime.h>
#include <math.h>
#include <float.h>

#define NN 8192
#define NE 65536
#define VPLANE ((size_t)NN * 576)

#define INV_SQRT128 0.08838834764831843f
#define INV_SQRT512 0.04419417382415922f
#define INV_SQRT3   0.5773502691896258f
#define INV_SQRT160 0.07905694150420949f
#define INV_SQRT32  0.17677669529663687f

#define SC_S   (0.125f * INV_SQRT128 * INV_SQRT160)
#define SC_V   (INV_SQRT32 * 0.125f * INV_SQRT160)
#define SC_P_S (INV_SQRT128)
#define SC_P_V (0.125f)
#define SC_C_S (0.125f * INV_SQRT512)
#define SC_C_V (0.125f * 0.0625f)

typedef unsigned long long u64;

__device__ __forceinline__ void fma2(u64& d, u64 a, u64 b) {
    asm("fma.rn.f32x2 %0, %1, %2, %0;" : "+l"(d) : "l"(a), "l"(b));
}
__device__ __forceinline__ u64 dupf(float x) {
    u64 r; asm("mov.b64 %0, {%1, %1};" : "=l"(r) : "r"(__float_as_uint(x))); return r;
}
__device__ __forceinline__ u64 pk2(float lo, float hi) {
    u64 r; asm("mov.b64 %0, {%1, %2};" : "=l"(r) : "r"(__float_as_uint(lo)), "r"(__float_as_uint(hi)));
    return r;
}

// ---------------- scratch ------------------------------------------------------
__device__ float g_xT[160 * NN];
__device__ float g_S[NN * 1088];
__device__ float g_V[3 * NN * 576];
__device__ float g_QKself[NN * 8];
__device__ float g_feat[NE * 160];
__device__ float g_logit[NE * 8];
__device__ float g_agg[NN * 1280];
__device__ float g_m[NN * 160];
__device__ int   g_cnt[NN];
__device__ int   g_offs[NN + 1];
__device__ int   g_cursor[NN];
__device__ int   g_elist[NE];
__device__ float g_Wts[64 * 1088];
__device__ float g_Wtv[32 * 576];
__device__ float g_Wcs[512 * 64];
__device__ float g_Wcv[256 * 32];

// ---------------- merged prep: weight packing + transpose + histogram --------------
__global__ void __launch_bounds__(256) k_prep(
        const float* __restrict__ Wq_s, const float* __restrict__ Wq_v,
        const float* __restrict__ Wk_s, const float* __restrict__ Wk_v,
        const float* __restrict__ Wp_s, const float* __restrict__ Wp_v,
        const float* __restrict__ Wv_s, const float* __restrict__ Wv_v,
        const float* __restrict__ Wm_s, const float* __restrict__ Wm_v,
        const float* __restrict__ x, float* __restrict__ xT,
        const int* __restrict__ ei) {
    __shared__ __align__(16) float sm[8192];
    int b = blockIdx.x, tid = threadIdx.x;
    if (b < 16) {
        int h = b & 7, self = b >> 3;
        float* Q = sm; float* Kx = sm + 4096;
        for (int i = tid; i < 4096; i += 256) {
            int a = i >> 6, j = i & 63;
            Q[i]  = Wq_s[a * 512 + h * 64 + j];
            int kr = self ? a : (64 + a);
            Kx[i] = Wk_s[kr * 512 + h * 64 + j];
        }
        __syncthreads();
        for (int i = tid; i < 4096; i += 256) {
            int a = i & 63, bb = i >> 6;
            float s = 0.f;
            for (int j = 0; j < 64; j++) s += Q[a * 64 + j] * Kx[bb * 64 + j];
            g_Wts[bb * 1088 + self * 512 + h * 64 + a] = s * SC_S;
        }
    } else if (b < 32) {
        int h = (b - 16) & 7, self = (b - 16) >> 3;
        float* Q = sm; float* Kx = sm + 1024;
        for (int i = tid; i < 1024; i += 256) {
            int a = i >> 5, j = i & 31;
            Q[i]  = Wq_v[a * 256 + h * 32 + j];
            int kr = self ? a : (32 + a);
            Kx[i] = Wk_v[kr * 256 + h * 32 + j];
        }
        __syncthreads();
        for (int i = tid; i < 1024; i += 256) {
            int a = i & 31, bb = i >> 5;
            float s = 0.f;
            for (int j = 0; j < 32; j++) s += Q[a * 32 + j] * Kx[bb * 32 + j];
            g_Wtv[bb * 576 + self * 256 + h * 32 + a] = s * SC_V;
        }
    } else if (b < 40) {
        int h = b - 32;
        float* V = sm; float* M = sm + 4096;
        for (int i = tid; i < 4096; i += 256) {
            int k = i >> 6, j = i & 63;
            V[i] = Wv_s[k * 512 + h * 64 + j];
            M[i] = Wm_s[(h * 64 + k) * 64 + j];
        }
        __syncthreads();
        for (int i = tid; i < 4096; i += 256) {
            int d = i & 63, k = i >> 6;
            float s = 0.f;
            for (int j = 0; j < 64; j++) s += V[k * 64 + j] * M[j * 64 + d];
            g_Wcs[(h * 64 + k) * 64 + d] = s * SC_C_S;
        }
    } else if (b < 48) {
        int h = b - 40;
        float* V = sm; float* M = sm + 1024;
        for (int i = tid; i < 1024; i += 256) {
            int k = i >> 5, j = i & 31;
            V[i] = Wv_v[k * 256 + h * 32 + j] + Wv_v[(32 + k) * 256 + h * 32 + j];
            M[i] = Wm_v[(h * 32 + k) * 32 + j];
        }
        __syncthreads();
        for (int i = tid; i < 1024; i += 256) {
            int d = i & 31, k = i >> 5;
            float s = 0.f;
            for (int j = 0; j < 32; j++) s += V[k * 32 + j] * M[j * 32 + d];
            g_Wcv[(h * 32 + k) * 32 + d] = s * SC_C_V;
        }
    } else if (b == 48) {
        for (int i = tid; i < 4096; i += 256) {
            int bb = i >> 6, c = i & 63;
            float w = (c < 32) ? Wp_s[bb * 32 + c] : Wp_s[(64 + bb) * 32 + (c - 32)];
            g_Wts[bb * 1088 + 1024 + c] = w * SC_P_S;
        }
        for (int i = tid; i < 2048; i += 256) {
            int bb = i >> 6, c = i & 63;
            float w = (c < 32) ? Wp_v[bb * 32 + c] : Wp_v[(32 + bb) * 32 + (c - 32)];
            g_Wtv[bb * 576 + 512 + c] = w * SC_P_V;
        }
    } else if (b < 1329) {
        float (*t)[33] = (float(*)[33])sm;
        int tx = tid & 31, ty = tid >> 5;
        int bi = b - 49;
        int n0 = (bi % 256) * 32, t0 = (bi / 256) * 32;
#pragma unroll
        for (int i = 0; i < 32; i += 8)
            t[ty + i][tx] = x[(size_t)(n0 + ty + i) * 160 + t0 + tx];
        __syncthreads();
#pragma unroll
        for (int i = 0; i < 32; i += 8)
            xT[(size_t)(t0 + ty + i) * 8192 + n0 + tx] = t[tx][ty + i];
    } else {
        int e = (b - 1329) * 256 + tid;
        atomicAdd(&g_cnt[ei[NE + e]], 1);
    }
}

// ---------------- node-projection GEMM + embedded CSR scan --------------------------
template<int K>
__device__ __forceinline__ void gemmT_body(
        const float* __restrict__ AT, int baseRow, int rowStride,
        const float* __restrict__ W, int N,
        float* __restrict__ C, int cRow, size_t planeStride,
        int bx, int by, int z, float* As, float* Ws, int tid) {
    int n0 = bx * 64, m0 = by * 128;
#pragma unroll
    for (int r = 0; r < (K * 128) / 1024; r++) {
        int idx = tid + r * 256;
        int k = idx >> 5, mp = idx & 31;
        *(float4*)&As[k * 128 + mp * 4] =
            *(const float4*)&AT[(size_t)(baseRow + z + k * rowStride) * 8192 + m0 + mp * 4];
    }
#pragma unroll
    for (int r = 0; r < (K * 64) / 1024; r++) {
        int idx = tid + r * 256;
        int k = idx >> 4, j = idx & 15;
        *(float4*)&Ws[k * 64 + j * 4] = *(const float4*)&W[(size_t)k * N + n0 + j * 4];
    }
    __syncthreads();
    int ty = tid >> 4, tx = tid & 15;
    u64 acc[4][4] = {};
#pragma unroll 8
    for (int k = 0; k < K; k++) {
        ulonglong2 a01 = *(const ulonglong2*)&As[k * 128 + ty * 8];
        ulonglong2 a23 = *(const ulonglong2*)&As[k * 128 + ty * 8 + 4];
        float4 b4 = *(const float4*)&Ws[k * 64 + tx * 4];
        u64 bb0 = dupf(b4.x), bb1 = dupf(b4.y), bb2 = dupf(b4.z), bb3 = dupf(b4.w);
        u64 ap[4] = {a01.x, a01.y, a23.x, a23.y};
#pragma unroll
        for (int q = 0; q < 4; q++) {
            fma2(acc[q][0], ap[q], bb0);
            fma2(acc[q][1], ap[q], bb1);
            fma2(acc[q][2], ap[q], bb2);
            fma2(acc[q][3], ap[q], bb3);
        }
    }
    float* Cb = C + (size_t)z * planeStride;
#pragma unroll
    for (int q = 0; q < 4; q++) {
        float2 c0 = *(float2*)&acc[q][0];
        float2 c1 = *(float2*)&acc[q][1];
        float2 c2 = *(float2*)&acc[q][2];
        float2 c3 = *(float2*)&acc[q][3];
        int r0 = m0 + ty * 8 + 2 * q;
        *(float4*)&Cb[(size_t)r0 * cRow + n0 + tx * 4]       = make_float4(c0.x, c1.x, c2.x, c3.x);
        *(float4*)&Cb[(size_t)(r0 + 1) * cRow + n0 + tx * 4] = make_float4(c0.y, c1.y, c2.y, c3.y);
    }
}

__global__ void __launch_bounds__(256) k_gemmT_m(const float* __restrict__ AT) {
    __shared__ __align__(16) float As[64 * 128];
    __shared__ __align__(16) float Ws[64 * 64];
    int b = blockIdx.x, tid = threadIdx.x;
    if (b < 1088) {
        gemmT_body<64>(AT, 0, 1, g_Wts, 1088, g_S, 1088, 0,
                       b % 17, b / 17, 0, As, Ws, tid);
    } else if (b < 2816) {
        int i = b - 1088;
        int z = i / 576, r = i % 576;
        gemmT_body<32>(AT, 64, 3, g_Wtv, 576, g_V, 576, VPLANE,
                       r % 9, r / 9, z, As, Ws, tid);
    } else {
        int* s = (int*)As;
        int* wsum = (int*)Ws;
        for (int i = tid; i < NN; i += 256) s[i] = g_cnt[i];
        __syncthreads();
        int base = tid * 32;
        int tot = 0;
        for (int i = 0; i < 32; i++) tot += s[base + i];
        int lane = tid & 31, w = tid >> 5;
        int incl = tot;
#pragma unroll
        for (int o = 1; o < 32; o <<= 1) {
            int y = __shfl_up_sync(0xffffffffu, incl, o);
            if (lane >= o) incl += y;
        }
        if (lane == 31) wsum[w] = incl;
        __syncthreads();
        if (tid == 0) {
            int r = 0;
#pragma unroll
            for (int j = 0; j < 8; j++) { int t = wsum[j]; wsum[j] = r; r += t; }
        }
        __syncthreads();
        int run = wsum[w] + (incl - tot);
        for (int i = 0; i < 32; i++) {
            g_offs[base + i] = run;
            g_cursor[base + i] = run;
            run += s[base + i];
        }
        if (tid == 255) g_offs[NN] = NE;
    }
}

// ---------------- merged final projections, f32x2 -----------------------------------
__global__ void __launch_bounds__(256) k_projm() {
    __shared__ __align__(16) float As[32 * 68];
    __shared__ __align__(16) float Ws[32 * 68];
    int tid = threadIdx.x;
    int b = blockIdx.x;
    const float* A; const float* W; float* C;
    int aRow, K, NC, cRow, cCol, m0;
    if (b < 128) {
        A = g_agg; aRow = 1280; K = 512; NC = 64;
        W = g_Wcs; C = g_m; cRow = 160; cCol = 1;
        m0 = b * 64;
    } else {
        int c = (b - 128) / 128, mt = (b - 128) % 128;
        A = g_agg + 512 + c * 256; aRow = 1280; K = 256; NC = 32;
        W = g_Wcv; C = g_m + 64 + c; cRow = 160; cCol = 3;
        m0 = mt * 64;
    }
    u64 acc[4][2] = {};
    int ty = tid >> 4, tx = tid & 15;

    for (int k0 = 0; k0 < K; k0 += 32) {
#pragma unroll
        for (int r = 0; r < 8; r++) {
            int l = tid + r * 256;
            int kk = l & 31, mm = l >> 5;
            As[kk * 68 + mm] = A[(size_t)(m0 + mm) * aRow + (k0 + kk)];
        }
#pragma unroll
        for (int r = 0; r < 8; r++) {
            int l = tid + r * 256;
            int kk = l >> 6, jj = l & 63;
            Ws[kk * 68 + jj] = (jj < NC) ? W[(size_t)(k0 + kk) * NC + jj] : 0.f;
        }
        __syncthreads();
#pragma unroll 8
        for (int k = 0; k < 32; k++) {
            float4 a4 = *(const float4*)&As[k * 68 + ty * 4];
            ulonglong2 bp = *(const ulonglong2*)&Ws[k * 68 + tx * 4];
            u64 aa0 = dupf(a4.x), aa1 = dupf(a4.y), aa2 = dupf(a4.z), aa3 = dupf(a4.w);
            fma2(acc[0][0], aa0, bp.x); fma2(acc[0][1], aa0, bp.y);
            fma2(acc[1][0], aa1, bp.x); fma2(acc[1][1], aa1, bp.y);
            fma2(acc[2][0], aa2, bp.x); fma2(acc[2][1], aa2, bp.y);
            fma2(acc[3][0], aa3, bp.x); fma2(acc[3][1], aa3, bp.y);
        }
        __syncthreads();
    }
#pragma unroll
    for (int i = 0; i < 4; i++) {
        int m = m0 + ty * 4 + i;
        float2 c01 = *(float2*)&acc[i][0];
        float2 c23 = *(float2*)&acc[i][1];
        int col = tx * 4;
        if (cCol == 1) {
            *(float4*)&C[(size_t)m * cRow + col] = make_float4(c01.x, c01.y, c23.x, c23.y);
        } else {
            if (col < NC) {
                C[(size_t)m * cRow + (col + 0) * 3] = c01.x;
                C[(size_t)m * cRow + (col + 1) * 3] = c01.y;
                C[(size_t)m * cRow + (col + 2) * 3] = c23.x;
                C[(size_t)m * cRow + (col + 3) * 3] = c23.y;
            }
        }
    }
}

// ---------------- edgeprep + qkself + scatter merged ---------------------------------
__global__ void __launch_bounds__(256) k_edge_qk(const float* __restrict__ rbf,
                                                 const float* __restrict__ rsh,
                                                 const int* __restrict__ ei,
                                                 const float* __restrict__ Wrbf,
                                                 const float* __restrict__ x) {
    int b = blockIdx.x, tid = threadIdx.x;
    if (b < 1024) {
        __shared__ float sW[1024];
        for (int l = tid; l < 1024; l += 256) sW[l] = Wrbf[l];
        __syncthreads();
        int wid = tid >> 5, lane = tid & 31;
        int d = lane;
#pragma unroll
        for (int it = 0; it < 8; it++) {
            int e = b * 64 + it * 8 + wid;
            int src = ei[e], dst = ei[NE + e];
            float ps = g_S[(size_t)src * 1088 + 1024 + d] + g_S[(size_t)dst * 1088 + 1056 + d];
            float pv[3];
#pragma unroll
            for (int c = 0; c < 3; c++)
                pv[c] = g_V[c * VPLANE + (size_t)src * 576 + 512 + d]
                      + g_V[c * VPLANE + (size_t)dst * 576 + 544 + d];
            float rval = (lane < 16) ? rbf[e * 16 + lane] : 0.f;
            float scal_s = 0.f, scal_v = 0.f;
#pragma unroll
            for (int bq = 0; bq < 16; bq++) {
                float rb = __shfl_sync(0xffffffffu, rval, bq);
                scal_s += rb * sW[bq * 64 + d];
                scal_v += rb * sW[bq * 64 + 32 + d];
            }
            float rs = rsh[e * 128 + d];
            float sph_s = rs * scal_s * ps;
            float sv[3];
#pragma unroll
            for (int c = 0; c < 3; c++)
                sv[c] = rsh[e * 128 + 32 + d * 3 + c] * scal_v * pv[c];
            float* f = g_feat + (size_t)e * 160;
            f[d]      = sph_s * sph_s;
            f[32 + d] = (sv[0] * sv[0] + sv[1] * sv[1] + sv[2] * sv[2]) * INV_SQRT3;
#pragma unroll
            for (int c = 0; c < 3; c++)
                f[64 + c * 32 + d] = sph_s * sv[c];
        }
    } else if (b < 2048) {
        __shared__ float s_q[8][160];
        int wid = tid >> 5, lane = tid & 31;
        int n = (b - 1024) * 8 + wid;
        const float4* xs = (const float4*)(x + (size_t)n * 160);
        ((float4*)s_q[wid])[lane] = xs[lane];
        if (lane < 8) ((float4*)s_q[wid])[32 + lane] = xs[32 + lane];
        __syncwarp();
        const float* xr = s_q[wid];
        const float* Sb = g_S + (size_t)n * 1088 + 512;
#pragma unroll
        for (int h = 0; h < 8; h++) {
            float a = Sb[h * 64 + lane] * xr[lane]
                    + Sb[h * 64 + 32 + lane] * xr[32 + lane];
#pragma unroll
            for (int c = 0; c < 3; c++)
                a += g_V[c * VPLANE + (size_t)n * 576 + 256 + h * 32 + lane]
                     * xr[64 + lane * 3 + c];
#pragma unroll
            for (int o = 16; o; o >>= 1) a += __shfl_xor_sync(0xffffffffu, a, o);
            if (lane == 0) g_QKself[n * 8 + h] = a;
        }
    } else {
        int e = (b - 2048) * 256 + tid;
        int pos = atomicAdd(&g_cursor[ei[NE + e]], 1);
        g_elist[pos] = e;
    }
}

// ---------------- fused attention + aggregation: warp/node, 4-edge batched gathers ----
__global__ void __launch_bounds__(256) k_attn_agg2(const float* __restrict__ x,
                                                   const int* __restrict__ ei) {
    __shared__ __align__(16) float s_xb[8][4][160];
    __shared__ float s_lg[8][512];
    const unsigned F = 0xffffffffu;
    int tid = threadIdx.x;
    int wid = tid >> 5, lane = tid & 31;
    int n = blockIdx.x * 8 + wid;
    int h = lane >> 2, p = lane & 3;     // compute-phase mapping
    int eb = lane >> 3, q = lane & 7;    // staging-phase mapping

    int s0 = g_offs[n], deg = g_offs[n + 1] - s0;
    float* lg = (deg <= 64) ? &s_lg[wid][0] : (g_logit + (size_t)s0 * 8);

    int e0 = 0, e1 = 0, src0 = 0, src1 = 0;
    if (lane < deg) e0 = g_elist[s0 + lane];
    if (lane + 32 < deg) e1 = g_elist[s0 + 32 + lane];
    if (lane < deg) src0 = ei[e0];
    if (lane + 32 < deg) src1 = ei[e1];

    float mymax = -FLT_MAX;
    {
        float tkf[40];
#pragma unroll
        for (int tt = 0; tt < 40; tt++) {
            int t = p * 40 + tt;
            if (t < 64)
                tkf[tt] = g_S[(size_t)n * 1088 + h * 64 + t];
            else {
                int j = t - 64;
                tkf[tt] = g_V[(j % 3) * VPLANE + (size_t)n * 576 + h * 32 + (j / 3)];
            }
        }
        u64 tk2[20];
#pragma unroll
        for (int i = 0; i < 20; i++) tk2[i] = pk2(tkf[2 * i], tkf[2 * i + 1]);

        for (int cs = 0; cs < deg; cs += 4) {
            // stage up to 4 edges' x rows (5 independent LDG.128 per lane)
            int ic = min(cs + eb, deg - 1);
            int src;
            if (cs < 64) {
                int selv = (cs < 32) ? src0 : src1;
                src = __shfl_sync(F, selv, ic & 31);
            } else {
                src = ei[g_elist[s0 + ic]];
            }
            const float4* xs = (const float4*)(x + (size_t)src * 160);
            float4 r0 = xs[q], r1 = xs[q + 8], r2 = xs[q + 16],
                   r3 = xs[q + 24], r4 = xs[q + 32];
            __syncwarp();   // previous batch's compute reads done before overwrite
            float4* sb = (float4*)s_xb[wid][eb];
            sb[q] = r0; sb[q + 8] = r1; sb[q + 16] = r2;
            sb[q + 24] = r3; sb[q + 32] = r4;
            __syncwarp();

            int nb = min(4, deg - cs);
            for (int j = 0; j < nb; j++) {
                const u64* xr2 = (const u64*)(s_xb[wid][j] + p * 40);
                u64 ac0 = 0, ac1 = 0, ac2 = 0, ac3 = 0;
#pragma unroll
                for (int qq = 0; qq < 20; qq += 4) {
                    fma2(ac0, tk2[qq + 0], xr2[qq + 0]);
                    fma2(ac1, tk2[qq + 1], xr2[qq + 1]);
                    fma2(ac2, tk2[qq + 2], xr2[qq + 2]);
                    fma2(ac3, tk2[qq + 3], xr2[qq + 3]);
                }
                float2 v0 = *(float2*)&ac0, v1 = *(float2*)&ac1;
                float2 v2 = *(float2*)&ac2, v3 = *(float2*)&ac3;
                float a = ((v0.x + v0.y) + (v1.x + v1.y)) + ((v2.x + v2.y) + (v3.x + v3.y));
                a += __shfl_xor_sync(F, a, 1);
                a += __shfl_xor_sync(F, a, 2);
                int srcj = __shfl_sync(F, src, j * 8);
                if (p == 0) {
                    a += g_QKself[srcj * 8 + h];
                    lg[(cs + j) * 8 + h] = a;
                    mymax = fmaxf(mymax, a);
                }
            }
        }
    }
    __syncwarp();

    if (p == 0 && deg > 0) {
        float den = 0.f;
        for (int i = 0; i < deg; i++) {
            float ex = expf(lg[i * 8 + h] - mymax);
            lg[i * 8 + h] = ex;
            den += ex;
        }
        float inv = 1.f / den;
        for (int i = 0; i < deg; i++) lg[i * 8 + h] *= inv;
    }
    __syncwarp();

    u64 accS[8] = {}, accV[8] = {};
    float accW[8] = {};

    for (int cs = 0; cs < deg; cs += 4) {
        // stage up to 4 edges' feat rows
        int ic = min(cs + eb, deg - 1);
        int e;
        if (cs < 64) {
            int selv = (cs < 32) ? e0 : e1;
            e = __shfl_sync(F, selv, ic & 31);
        } else {
            e = g_elist[s0 + ic];
        }
        const float4* fr4 = (const float4*)(g_feat + (size_t)e * 160);
        float4 r0 = fr4[q], r1 = fr4[q + 8], r2 = fr4[q + 16],
               r3 = fr4[q + 24], r4 = fr4[q + 32];
        __syncwarp();
        float4* sb = (float4*)s_xb[wid][eb];
        sb[q] = r0; sb[q + 8] = r1; sb[q + 16] = r2;
        sb[q + 24] = r3; sb[q + 32] = r4;
        __syncwarp();

        int nb = min(4, deg - cs);
        for (int j = 0; j < nb; j++) {
            const float* fr = s_xb[wid][j];
            float f0  = fr[lane];
            float f1  = fr[32 + lane];
            float fv0 = fr[64 + lane];
            float fv1 = fr[96 + lane];
            float fv2 = fr[128 + lane];
            u64 fS = pk2(f0, f1);
            u64 fV = pk2(fv0, fv1);
            const float* ar = lg + (cs + j) * 8;
#pragma unroll
            for (int hh = 0; hh < 8; hh++) {
                float at = ar[hh];
                u64 at2 = dupf(at);
                fma2(accS[hh], fS, at2);
                fma2(accV[hh], fV, at2);
                accW[hh] += at * fv2;
            }
        }
    }
    float* ao = g_agg + (size_t)n * 1280;
#pragma unroll
    for (int hh = 0; hh < 8; hh++) {
        float2 s = *(float2*)&accS[hh];
        ao[(2 * hh) * 32 + lane]      = s.x;
        ao[(2 * hh + 1) * 32 + lane]  = s.y;
        float2 v = *(float2*)&accV[hh];
        ao[(16 + hh) * 32 + lane]     = v.x;
        ao[(24 + hh) * 32 + lane]     = v.y;
        ao[(32 + hh) * 32 + lane]     = accW[hh];
    }
}

// ---------------- NormGate + output --------------------------------------------------
__global__ void __launch_bounds__(256) k_normgate(const float* __restrict__ ln_g,
                                                  const float* __restrict__ ln_b,
                                                  const float* __restrict__ W1,
                                                  const float* __restrict__ b1,
                                                  const float* __restrict__ W2,
                                                  const float* __restrict__ b2,
                                                  float* __restrict__ out) {
    __shared__ float sW1[96 * 96];
    __shared__ float sX[8][96];
    __shared__ float sH[8][96];
    int tid = threadIdx.x;
    int w = tid >> 5, lane = tid & 31;
    for (int i = tid; i < 9216; i += 256) sW1[i] = W1[i];
    __syncthreads();

    for (int sub = 0; sub < 4; sub++) {
        int n = blockIdx.x * 32 + w * 4 + sub;
        const float* mrow = g_m + (size_t)n * 160;
        float ms0 = mrow[lane], ms1 = mrow[32 + lane];
        float v0 = mrow[64 + lane * 3 + 0];
        float v1 = mrow[64 + lane * 3 + 1];
        float v2 = mrow[64 + lane * 3 + 2];
        float n00 = fabsf(ms0), n01 = fabsf(ms1);
        float n02 = sqrtf(v0 * v0 + v1 * v1 + v2 * v2);
        float s = n00 + n01 + n02;
        float s2 = n00 * n00 + n01 * n01 + n02 * n02;
#pragma unroll
        for (int o = 16; o; o >>= 1) {
            s  += __shfl_xor_sync(0xffffffffu, s, o);
            s2 += __shfl_xor_sync(0xffffffffu, s2, o);
        }
        float mu = s * (1.f / 96.f);
        float var = s2 * (1.f / 96.f) - mu * mu;
        float rstd = rsqrtf(var + 1e-5f);
        sX[w][lane]      = (n00 - mu) * rstd * ln_g[lane]      + ln_b[lane];
        sX[w][lane + 32] = (n01 - mu) * rstd * ln_g[lane + 32] + ln_b[lane + 32];
        sX[w][lane + 64] = (n02 - mu) * rstd * ln_g[lane + 64] + ln_b[lane + 64];
        __syncwarp();
#pragma unroll
        for (int t = 0; t < 3; t++) {
            int jp = lane + t * 32;
            float hs = b1[jp];
            for (int j = 0; j < 96; j++) hs += sX[w][j] * sW1[j * 96 + jp];
            sH[w][jp] = hs / (1.f + expf(-hs));
        }
        __syncwarp();
        float n0arr[3] = {n00, n01, n02};
        float f[3];
#pragma unroll
        for (int t = 0; t < 3; t++) {
            int jp = lane + t * 32;
            float gs = b2[jp];
            for (int j = 0; j < 96; j++) gs += sH[w][j] * W2[j * 96 + jp];
            float gg = gs / (1.f + expf(-gs));
            f[t] = gg / (n0arr[t] + 1e-6f);
        }
        out[n * 160 + lane]      = ms0 * f[0];
        out[n * 160 + 32 + lane] = ms1 * f[1];
        out[n * 160 + 64 + lane * 3 + 0] = v0 * f[2];
        out[n * 160 + 64 + lane * 3 + 1] = v1 * f[2];
        out[n * 160 + 64 + lane * 3 + 2] = v2 * f[2];
        __syncwarp();
    }
}

// ---------------- launch ----------------------------------------------------------------
extern "C" void kernel_launch(void* const* d_in, const int* in_sizes, int n_in,
                              void* d_out, int out_size) {
    const float* pseduo_x = (const float*)d_in[0];
    const float* rbf   = (const float*)d_in[1];
    const float* rsh   = (const float*)d_in[2];
    const int*   ei    = (const int*)d_in[3];
    const float* Wq_s  = (const float*)d_in[4];
    const float* Wq_v  = (const float*)d_in[5];
    const float* Wk_s  = (const float*)d_in[6];
    const float* Wk_v  = (const float*)d_in[7];
    const float* Wp_s  = (const float*)d_in[8];
    const float* Wp_v  = (const float*)d_in[9];
    const float* Wrbf  = (const float*)d_in[10];
    const float* Wv_s  = (const float*)d_in[11];
    const float* Wv_v  = (const float*)d_in[12];
    const float* Wm_s  = (const float*)d_in[13];
    const float* Wm_v  = (const float*)d_in[14];
    const float* ln_g  = (const float*)d_in[15];
    const float* ln_b  = (const float*)d_in[16];
    const float* W1    = (const float*)d_in[17];
    const float* b1    = (const float*)d_in[18];
    const float* W2    = (const float*)d_in[19];
    const float* b2    = (const float*)d_in[20];
    float* out = (float*)d_out;

    void* p;
    cudaGetSymbolAddress(&p, g_xT);  float* XT  = (float*)p;
    cudaGetSymbolAddress(&p, g_cnt); int*   CNT = (int*)p;

    cudaMemsetAsync(CNT, 0, NN * sizeof(int));
    k_prep<<<1585, 256>>>(Wq_s, Wq_v, Wk_s, Wk_v, Wp_s, Wp_v,
                          Wv_s, Wv_v, Wm_s, Wm_v, pseduo_x, XT, ei);

    k_gemmT_m<<<2817, 256>>>(XT);

    k_edge_qk<<<2304, 256>>>(rbf, rsh, ei, Wrbf, pseduo_x);

    k_attn_agg2<<<1024, 256>>>(pseduo_x, ei);

    k_projm<<<512, 256>>>();
    k_normgate<<<256, 256>>>(ln_g, ln_b, W1, b1, W2, b2, out);
}

// round 17
// speedup vs baseline: 1.4579x; 1.4579x over previous
#include <cuda_runtime.h>
#include <math.h>
#include <float.h>

#define NN 8192
#define NE 65536
#define VPLANE ((size_t)NN * 576)

#define INV_SQRT128 0.08838834764831843f
#define INV_SQRT512 0.04419417382415922f
#define INV_SQRT3   0.5773502691896258f
#define INV_SQRT160 0.07905694150420949f
#define INV_SQRT32  0.17677669529663687f

#define SC_S   (0.125f * INV_SQRT128 * INV_SQRT160)
#define SC_V   (INV_SQRT32 * 0.125f * INV_SQRT160)
#define SC_P_S (INV_SQRT128)
#define SC_P_V (0.125f)
#define SC_C_S (0.125f * INV_SQRT512)
#define SC_C_V (0.125f * 0.0625f)

typedef unsigned long long u64;

__device__ __forceinline__ void fma2(u64& d, u64 a, u64 b) {
    asm("fma.rn.f32x2 %0, %1, %2, %0;" : "+l"(d) : "l"(a), "l"(b));
}
__device__ __forceinline__ u64 dupf(float x) {
    u64 r; asm("mov.b64 %0, {%1, %1};" : "=l"(r) : "r"(__float_as_uint(x))); return r;
}
__device__ __forceinline__ u64 pk2(float lo, float hi) {
    u64 r; asm("mov.b64 %0, {%1, %2};" : "=l"(r) : "r"(__float_as_uint(lo)), "r"(__float_as_uint(hi)));
    return r;
}

// ---------------- scratch ------------------------------------------------------
__device__ float g_xT[160 * NN];
__device__ float g_S[NN * 1088];
__device__ float g_V[3 * NN * 576];
__device__ float g_QKself[NN * 8];
__device__ float g_feat[NE * 160];
__device__ float g_logit[NE * 8];
__device__ float g_agg[NN * 1280];
__device__ float g_m[NN * 160];
__device__ int   g_cnt[NN];
__device__ int   g_offs[NN + 1];
__device__ int   g_cursor[NN];
__device__ int   g_elist[NE];
__device__ float g_Wts[64 * 1088];
__device__ float g_Wtv[32 * 576];
__device__ float g_Wcs[512 * 64];
__device__ float g_Wcv[256 * 32];

// ---------------- merged prep: weight packing + transpose + histogram --------------
__global__ void __launch_bounds__(256) k_prep(
        const float* __restrict__ Wq_s, const float* __restrict__ Wq_v,
        const float* __restrict__ Wk_s, const float* __restrict__ Wk_v,
        const float* __restrict__ Wp_s, const float* __restrict__ Wp_v,
        const float* __restrict__ Wv_s, const float* __restrict__ Wv_v,
        const float* __restrict__ Wm_s, const float* __restrict__ Wm_v,
        const float* __restrict__ x, float* __restrict__ xT,
        const int* __restrict__ ei) {
    __shared__ __align__(16) float sm[8192];
    int b = blockIdx.x, tid = threadIdx.x;
    if (b < 16) {
        int h = b & 7, self = b >> 3;
        float* Q = sm; float* Kx = sm + 4096;
        for (int i = tid; i < 4096; i += 256) {
            int a = i >> 6, j = i & 63;
            Q[i]  = Wq_s[a * 512 + h * 64 + j];
            int kr = self ? a : (64 + a);
            Kx[i] = Wk_s[kr * 512 + h * 64 + j];
        }
        __syncthreads();
        for (int i = tid; i < 4096; i += 256) {
            int a = i & 63, bb = i >> 6;
            float s = 0.f;
            for (int j = 0; j < 64; j++) s += Q[a * 64 + j] * Kx[bb * 64 + j];
            g_Wts[bb * 1088 + self * 512 + h * 64 + a] = s * SC_S;
        }
    } else if (b < 32) {
        int h = (b - 16) & 7, self = (b - 16) >> 3;
        float* Q = sm; float* Kx = sm + 1024;
        for (int i = tid; i < 1024; i += 256) {
            int a = i >> 5, j = i & 31;
            Q[i]  = Wq_v[a * 256 + h * 32 + j];
            int kr = self ? a : (32 + a);
            Kx[i] = Wk_v[kr * 256 + h * 32 + j];
        }
        __syncthreads();
        for (int i = tid; i < 1024; i += 256) {
            int a = i & 31, bb = i >> 5;
            float s = 0.f;
            for (int j = 0; j < 32; j++) s += Q[a * 32 + j] * Kx[bb * 32 + j];
            g_Wtv[bb * 576 + self * 256 + h * 32 + a] = s * SC_V;
        }
    } else if (b < 40) {
        int h = b - 32;
        float* V = sm; float* M = sm + 4096;
        for (int i = tid; i < 4096; i += 256) {
            int k = i >> 6, j = i & 63;
            V[i] = Wv_s[k * 512 + h * 64 + j];
            M[i] = Wm_s[(h * 64 + k) * 64 + j];
        }
        __syncthreads();
        for (int i = tid; i < 4096; i += 256) {
            int d = i & 63, k = i >> 6;
            float s = 0.f;
            for (int j = 0; j < 64; j++) s += V[k * 64 + j] * M[j * 64 + d];
            g_Wcs[(h * 64 + k) * 64 + d] = s * SC_C_S;
        }
    } else if (b < 48) {
        int h = b - 40;
        float* V = sm; float* M = sm + 1024;
        for (int i = tid; i < 1024; i += 256) {
            int k = i >> 5, j = i & 31;
            V[i] = Wv_v[k * 256 + h * 32 + j] + Wv_v[(32 + k) * 256 + h * 32 + j];
            M[i] = Wm_v[(h * 32 + k) * 32 + j];
        }
        __syncthreads();
        for (int i = tid; i < 1024; i += 256) {
            int d = i & 31, k = i >> 5;
            float s = 0.f;
            for (int j = 0; j < 32; j++) s += V[k * 32 + j] * M[j * 32 + d];
            g_Wcv[(h * 32 + k) * 32 + d] = s * SC_C_V;
        }
    } else if (b == 48) {
        for (int i = tid; i < 4096; i += 256) {
            int bb = i >> 6, c = i & 63;
            float w = (c < 32) ? Wp_s[bb * 32 + c] : Wp_s[(64 + bb) * 32 + (c - 32)];
            g_Wts[bb * 1088 + 1024 + c] = w * SC_P_S;
        }
        for (int i = tid; i < 2048; i += 256) {
            int bb = i >> 6, c = i & 63;
            float w = (c < 32) ? Wp_v[bb * 32 + c] : Wp_v[(32 + bb) * 32 + (c - 32)];
            g_Wtv[bb * 576 + 512 + c] = w * SC_P_V;
        }
    } else if (b < 1329) {
        float (*t)[33] = (float(*)[33])sm;
        int tx = tid & 31, ty = tid >> 5;
        int bi = b - 49;
        int n0 = (bi % 256) * 32, t0 = (bi / 256) * 32;
#pragma unroll
        for (int i = 0; i < 32; i += 8)
            t[ty + i][tx] = x[(size_t)(n0 + ty + i) * 160 + t0 + tx];
        __syncthreads();
#pragma unroll
        for (int i = 0; i < 32; i += 8)
            xT[(size_t)(t0 + ty + i) * 8192 + n0 + tx] = t[tx][ty + i];
    } else {
        int e = (b - 1329) * 256 + tid;
        atomicAdd(&g_cnt[ei[NE + e]], 1);
    }
}

// ---------------- node-projection GEMM + embedded CSR scan --------------------------
template<int K>
__device__ __forceinline__ void gemmT_body(
        const float* __restrict__ AT, int baseRow, int rowStride,
        const float* __restrict__ W, int N,
        float* __restrict__ C, int cRow, size_t planeStride,
        int bx, int by, int z, float* As, float* Ws, int tid) {
    int n0 = bx * 64, m0 = by * 128;
#pragma unroll
    for (int r = 0; r < (K * 128) / 1024; r++) {
        int idx = tid + r * 256;
        int k = idx >> 5, mp = idx & 31;
        *(float4*)&As[k * 128 + mp * 4] =
            *(const float4*)&AT[(size_t)(baseRow + z + k * rowStride) * 8192 + m0 + mp * 4];
    }
#pragma unroll
    for (int r = 0; r < (K * 64) / 1024; r++) {
        int idx = tid + r * 256;
        int k = idx >> 4, j = idx & 15;
        *(float4*)&Ws[k * 64 + j * 4] = *(const float4*)&W[(size_t)k * N + n0 + j * 4];
    }
    __syncthreads();
    int ty = tid >> 4, tx = tid & 15;
    u64 acc[4][4] = {};
#pragma unroll 8
    for (int k = 0; k < K; k++) {
        ulonglong2 a01 = *(const ulonglong2*)&As[k * 128 + ty * 8];
        ulonglong2 a23 = *(const ulonglong2*)&As[k * 128 + ty * 8 + 4];
        float4 b4 = *(const float4*)&Ws[k * 64 + tx * 4];
        u64 bb0 = dupf(b4.x), bb1 = dupf(b4.y), bb2 = dupf(b4.z), bb3 = dupf(b4.w);
        u64 ap[4] = {a01.x, a01.y, a23.x, a23.y};
#pragma unroll
        for (int q = 0; q < 4; q++) {
            fma2(acc[q][0], ap[q], bb0);
            fma2(acc[q][1], ap[q], bb1);
            fma2(acc[q][2], ap[q], bb2);
            fma2(acc[q][3], ap[q], bb3);
        }
    }
    float* Cb = C + (size_t)z * planeStride;
#pragma unroll
    for (int q = 0; q < 4; q++) {
        float2 c0 = *(float2*)&acc[q][0];
        float2 c1 = *(float2*)&acc[q][1];
        float2 c2 = *(float2*)&acc[q][2];
        float2 c3 = *(float2*)&acc[q][3];
        int r0 = m0 + ty * 8 + 2 * q;
        *(float4*)&Cb[(size_t)r0 * cRow + n0 + tx * 4]       = make_float4(c0.x, c1.x, c2.x, c3.x);
        *(float4*)&Cb[(size_t)(r0 + 1) * cRow + n0 + tx * 4] = make_float4(c0.y, c1.y, c2.y, c3.y);
    }
}

__global__ void __launch_bounds__(256) k_gemmT_m(const float* __restrict__ AT) {
    __shared__ __align__(16) float As[64 * 128];
    __shared__ __align__(16) float Ws[64 * 64];
    int b = blockIdx.x, tid = threadIdx.x;
    if (b < 1088) {
        gemmT_body<64>(AT, 0, 1, g_Wts, 1088, g_S, 1088, 0,
                       b % 17, b / 17, 0, As, Ws, tid);
    } else if (b < 2816) {
        int i = b - 1088;
        int z = i / 576, r = i % 576;
        gemmT_body<32>(AT, 64, 3, g_Wtv, 576, g_V, 576, VPLANE,
                       r % 9, r / 9, z, As, Ws, tid);
    } else {
        int* s = (int*)As;
        int* wsum = (int*)Ws;
        for (int i = tid; i < NN; i += 256) s[i] = g_cnt[i];
        __syncthreads();
        int base = tid * 32;
        int tot = 0;
        for (int i = 0; i < 32; i++) tot += s[base + i];
        int lane = tid & 31, w = tid >> 5;
        int incl = tot;
#pragma unroll
        for (int o = 1; o < 32; o <<= 1) {
            int y = __shfl_up_sync(0xffffffffu, incl, o);
            if (lane >= o) incl += y;
        }
        if (lane == 31) wsum[w] = incl;
        __syncthreads();
        if (tid == 0) {
            int r = 0;
#pragma unroll
            for (int j = 0; j < 8; j++) { int t = wsum[j]; wsum[j] = r; r += t; }
        }
        __syncthreads();
        int run = wsum[w] + (incl - tot);
        for (int i = 0; i < 32; i++) {
            g_offs[base + i] = run;
            g_cursor[base + i] = run;
            run += s[base + i];
        }
        if (tid == 255) g_offs[NN] = NE;
    }
}

// ---------------- merged final projections, f32x2 -----------------------------------
__global__ void __launch_bounds__(256) k_projm() {
    __shared__ __align__(16) float As[32 * 68];
    __shared__ __align__(16) float Ws[32 * 68];
    int tid = threadIdx.x;
    int b = blockIdx.x;
    const float* A; const float* W; float* C;
    int aRow, K, NC, cRow, cCol, m0;
    if (b < 128) {
        A = g_agg; aRow = 1280; K = 512; NC = 64;
        W = g_Wcs; C = g_m; cRow = 160; cCol = 1;
        m0 = b * 64;
    } else {
        int c = (b - 128) / 128, mt = (b - 128) % 128;
        A = g_agg + 512 + c * 256; aRow = 1280; K = 256; NC = 32;
        W = g_Wcv; C = g_m + 64 + c; cRow = 160; cCol = 3;
        m0 = mt * 64;
    }
    u64 acc[4][2] = {};
    int ty = tid >> 4, tx = tid & 15;

    for (int k0 = 0; k0 < K; k0 += 32) {
#pragma unroll
        for (int r = 0; r < 8; r++) {
            int l = tid + r * 256;
            int kk = l & 31, mm = l >> 5;
            As[kk * 68 + mm] = A[(size_t)(m0 + mm) * aRow + (k0 + kk)];
        }
#pragma unroll
        for (int r = 0; r < 8; r++) {
            int l = tid + r * 256;
            int kk = l >> 6, jj = l & 63;
            Ws[kk * 68 + jj] = (jj < NC) ? W[(size_t)(k0 + kk) * NC + jj] : 0.f;
        }
        __syncthreads();
#pragma unroll 8
        for (int k = 0; k < 32; k++) {
            float4 a4 = *(const float4*)&As[k * 68 + ty * 4];
            ulonglong2 bp = *(const ulonglong2*)&Ws[k * 68 + tx * 4];
            u64 aa0 = dupf(a4.x), aa1 = dupf(a4.y), aa2 = dupf(a4.z), aa3 = dupf(a4.w);
            fma2(acc[0][0], aa0, bp.x); fma2(acc[0][1], aa0, bp.y);
            fma2(acc[1][0], aa1, bp.x); fma2(acc[1][1], aa1, bp.y);
            fma2(acc[2][0], aa2, bp.x); fma2(acc[2][1], aa2, bp.y);
            fma2(acc[3][0], aa3, bp.x); fma2(acc[3][1], aa3, bp.y);
        }
        __syncthreads();
    }
#pragma unroll
    for (int i = 0; i < 4; i++) {
        int m = m0 + ty * 4 + i;
        float2 c01 = *(float2*)&acc[i][0];
        float2 c23 = *(float2*)&acc[i][1];
        int col = tx * 4;
        if (cCol == 1) {
            *(float4*)&C[(size_t)m * cRow + col] = make_float4(c01.x, c01.y, c23.x, c23.y);
        } else {
            if (col < NC) {
                C[(size_t)m * cRow + (col + 0) * 3] = c01.x;
                C[(size_t)m * cRow + (col + 1) * 3] = c01.y;
                C[(size_t)m * cRow + (col + 2) * 3] = c23.x;
                C[(size_t)m * cRow + (col + 3) * 3] = c23.y;
            }
        }
    }
}

// ---------------- edgeprep + qkself + scatter merged ---------------------------------
__global__ void __launch_bounds__(256) k_edge_qk(const float* __restrict__ rbf,
                                                 const float* __restrict__ rsh,
                                                 const int* __restrict__ ei,
                                                 const float* __restrict__ Wrbf,
                                                 const float* __restrict__ x) {
    int b = blockIdx.x, tid = threadIdx.x;
    if (b < 1024) {
        __shared__ float sW[1024];
        for (int l = tid; l < 1024; l += 256) sW[l] = Wrbf[l];
        __syncthreads();
        int wid = tid >> 5, lane = tid & 31;
        int d = lane;
#pragma unroll
        for (int it = 0; it < 8; it++) {
            int e = b * 64 + it * 8 + wid;
            int src = ei[e], dst = ei[NE + e];
            float ps = g_S[(size_t)src * 1088 + 1024 + d] + g_S[(size_t)dst * 1088 + 1056 + d];
            float pv[3];
#pragma unroll
            for (int c = 0; c < 3; c++)
                pv[c] = g_V[c * VPLANE + (size_t)src * 576 + 512 + d]
                      + g_V[c * VPLANE + (size_t)dst * 576 + 544 + d];
            float rval = (lane < 16) ? rbf[e * 16 + lane] : 0.f;
            float scal_s = 0.f, scal_v = 0.f;
#pragma unroll
            for (int bq = 0; bq < 16; bq++) {
                float rb = __shfl_sync(0xffffffffu, rval, bq);
                scal_s += rb * sW[bq * 64 + d];
                scal_v += rb * sW[bq * 64 + 32 + d];
            }
            float rs = rsh[e * 128 + d];
            float sph_s = rs * scal_s * ps;
            float sv[3];
#pragma unroll
            for (int c = 0; c < 3; c++)
                sv[c] = rsh[e * 128 + 32 + d * 3 + c] * scal_v * pv[c];
            float* f = g_feat + (size_t)e * 160;
            f[d]      = sph_s * sph_s;
            f[32 + d] = (sv[0] * sv[0] + sv[1] * sv[1] + sv[2] * sv[2]) * INV_SQRT3;
#pragma unroll
            for (int c = 0; c < 3; c++)
                f[64 + c * 32 + d] = sph_s * sv[c];
        }
    } else if (b < 2048) {
        __shared__ float s_q[8][160];
        int wid = tid >> 5, lane = tid & 31;
        int n = (b - 1024) * 8 + wid;
        const float4* xs = (const float4*)(x + (size_t)n * 160);
        ((float4*)s_q[wid])[lane] = xs[lane];
        if (lane < 8) ((float4*)s_q[wid])[32 + lane] = xs[32 + lane];
        __syncwarp();
        const float* xr = s_q[wid];
        const float* Sb = g_S + (size_t)n * 1088 + 512;
#pragma unroll
        for (int h = 0; h < 8; h++) {
            float a = Sb[h * 64 + lane] * xr[lane]
                    + Sb[h * 64 + 32 + lane] * xr[32 + lane];
#pragma unroll
            for (int c = 0; c < 3; c++)
                a += g_V[c * VPLANE + (size_t)n * 576 + 256 + h * 32 + lane]
                     * xr[64 + lane * 3 + c];
#pragma unroll
            for (int o = 16; o; o >>= 1) a += __shfl_xor_sync(0xffffffffu, a, o);
            if (lane == 0) g_QKself[n * 8 + h] = a;
        }
    } else {
        int e = (b - 2048) * 256 + tid;
        int pos = atomicAdd(&g_cursor[ei[NE + e]], 1);
        g_elist[pos] = e;
    }
}

// ---------------- fused attention + aggregation: warp/node, dbl-buffer + prefetch -----
__global__ void __launch_bounds__(256) k_attn_agg2(const float* __restrict__ x,
                                                   const int* __restrict__ ei) {
    __shared__ __align__(16) float s_x[8][2][160];
    __shared__ float s_lg[8][512];
    const unsigned F = 0xffffffffu;
    int tid = threadIdx.x;
    int wid = tid >> 5, lane = tid & 31;
    int n = blockIdx.x * 8 + wid;
    int h = lane >> 2, p = lane & 3;

    int s0 = g_offs[n], deg = g_offs[n + 1] - s0;
    float* lg = (deg <= 64) ? &s_lg[wid][0] : (g_logit + (size_t)s0 * 8);

    int e0 = 0, e1 = 0, src0 = 0, src1 = 0;
    if (lane < deg) e0 = g_elist[s0 + lane];
    if (lane + 32 < deg) e1 = g_elist[s0 + 32 + lane];
    if (lane < deg) src0 = ei[e0];
    if (lane + 32 < deg) src1 = ei[e1];

    float mymax = -FLT_MAX;
    {
        float tkf[40];
#pragma unroll
        for (int tt = 0; tt < 40; tt++) {
            int t = p * 40 + tt;
            if (t < 64)
                tkf[tt] = g_S[(size_t)n * 1088 + h * 64 + t];
            else {
                int j = t - 64;
                tkf[tt] = g_V[(j % 3) * VPLANE + (size_t)n * 576 + h * 32 + (j / 3)];
            }
        }
        u64 tk2[20];
#pragma unroll
        for (int i = 0; i < 20; i++) tk2[i] = pk2(tkf[2 * i], tkf[2 * i + 1]);

        if (deg > 0) {
            int src = __shfl_sync(F, src0, 0);
            const float4* xs = (const float4*)(x + (size_t)src * 160);
            ((float4*)s_x[wid][0])[lane] = xs[lane];
            if (lane < 8) ((float4*)s_x[wid][0])[32 + lane] = xs[32 + lane];
        }
        __syncwarp();

        for (int i = 0; i < deg; i++) {
            int src;
            if (i < 64) src = __shfl_sync(F, (i < 32) ? src0 : src1, i & 31);
            else {
                int ss = 0;
                if (lane == 0) ss = ei[g_elist[s0 + i]];
                src = __shfl_sync(F, ss, 0);
            }
            float4 nf0, nf1;
            int havenext = (i + 1 < deg);
            if (havenext) {
                int nsrc;
                int j = i + 1;
                if (j < 64) nsrc = __shfl_sync(F, (j < 32) ? src0 : src1, j & 31);
                else {
                    int ss = 0;
                    if (lane == 0) ss = ei[g_elist[s0 + j]];
                    nsrc = __shfl_sync(F, ss, 0);
                }
                const float4* nxs = (const float4*)(x + (size_t)nsrc * 160);
                nf0 = nxs[lane];
                if (lane < 8) nf1 = nxs[32 + lane];
            }
            const u64* xr2 = (const u64*)(s_x[wid][i & 1] + p * 40);
            u64 ac0 = 0, ac1 = 0, ac2 = 0, ac3 = 0;
#pragma unroll
            for (int q = 0; q < 20; q += 4) {
                fma2(ac0, tk2[q + 0], xr2[q + 0]);
                fma2(ac1, tk2[q + 1], xr2[q + 1]);
                fma2(ac2, tk2[q + 2], xr2[q + 2]);
                fma2(ac3, tk2[q + 3], xr2[q + 3]);
            }
            float2 v0 = *(float2*)&ac0, v1 = *(float2*)&ac1;
            float2 v2 = *(float2*)&ac2, v3 = *(float2*)&ac3;
            float a = ((v0.x + v0.y) + (v1.x + v1.y)) + ((v2.x + v2.y) + (v3.x + v3.y));
            a += __shfl_xor_sync(F, a, 1);
            a += __shfl_xor_sync(F, a, 2);
            if (p == 0) {
                a += g_QKself[src * 8 + h];
                lg[i * 8 + h] = a;
                mymax = fmaxf(mymax, a);
            }
            if (havenext) {
                ((float4*)s_x[wid][(i + 1) & 1])[lane] = nf0;
                if (lane < 8) ((float4*)s_x[wid][(i + 1) & 1])[32 + lane] = nf1;
            }
            __syncwarp();
        }
    }

    if (p == 0 && deg > 0) {
        float den = 0.f;
        for (int i = 0; i < deg; i++) {
            float ex = expf(lg[i * 8 + h] - mymax);
            lg[i * 8 + h] = ex;
            den += ex;
        }
        float inv = 1.f / den;
        for (int i = 0; i < deg; i++) lg[i * 8 + h] *= inv;
    }
    __syncwarp();

    u64 accS[8] = {}, accV[8] = {};
    float accW[8] = {};

    float f0, f1, fv0, fv1, fv2;
    if (deg > 0) {
        int e = __shfl_sync(F, e0, 0);
        const float* fr = g_feat + (size_t)e * 160;
        f0 = fr[lane]; f1 = fr[32 + lane];
        fv0 = fr[64 + lane]; fv1 = fr[96 + lane]; fv2 = fr[128 + lane];
    }
    for (int i = 0; i < deg; i++) {
        float nf0v, nf1v, nv0, nv1, nv2;
        int havenext = (i + 1 < deg);
        if (havenext) {
            int j = i + 1, e;
            if (j < 64) e = __shfl_sync(F, (j < 32) ? e0 : e1, j & 31);
            else {
                int ee = 0;
                if (lane == 0) ee = g_elist[s0 + j];
                e = __shfl_sync(F, ee, 0);
            }
            const float* fr = g_feat + (size_t)e * 160;
            nf0v = fr[lane]; nf1v = fr[32 + lane];
            nv0 = fr[64 + lane]; nv1 = fr[96 + lane]; nv2 = fr[128 + lane];
        }
        u64 fS = pk2(f0, f1);
        u64 fV = pk2(fv0, fv1);
        const float* ar = lg + i * 8;
#pragma unroll
        for (int hh = 0; hh < 8; hh++) {
            float at = ar[hh];
            u64 at2 = dupf(at);
            fma2(accS[hh], fS, at2);
            fma2(accV[hh], fV, at2);
            accW[hh] += at * fv2;
        }
        if (havenext) { f0 = nf0v; f1 = nf1v; fv0 = nv0; fv1 = nv1; fv2 = nv2; }
    }
    float* ao = g_agg + (size_t)n * 1280;
#pragma unroll
    for (int hh = 0; hh < 8; hh++) {
        float2 s = *(float2*)&accS[hh];
        ao[(2 * hh) * 32 + lane]      = s.x;
        ao[(2 * hh + 1) * 32 + lane]  = s.y;
        float2 v = *(float2*)&accV[hh];
        ao[(16 + hh) * 32 + lane]     = v.x;
        ao[(24 + hh) * 32 + lane]     = v.y;
        ao[(32 + hh) * 32 + lane]     = accW[hh];
    }
}

// ---------------- NormGate + output --------------------------------------------------
__global__ void __launch_bounds__(256) k_normgate(const float* __restrict__ ln_g,
                                                  const float* __restrict__ ln_b,
                                                  const float* __restrict__ W1,
                                                  const float* __restrict__ b1,
                                                  const float* __restrict__ W2,
                                                  const float* __restrict__ b2,
                                                  float* __restrict__ out) {
    __shared__ float sW1[96 * 96];
    __shared__ float sX[8][96];
    __shared__ float sH[8][96];
    int tid = threadIdx.x;
    int w = tid >> 5, lane = tid & 31;
    for (int i = tid; i < 9216; i += 256) sW1[i] = W1[i];
    __syncthreads();

    for (int sub = 0; sub < 4; sub++) {
        int n = blockIdx.x * 32 + w * 4 + sub;
        const float* mrow = g_m + (size_t)n * 160;
        float ms0 = mrow[lane], ms1 = mrow[32 + lane];
        float v0 = mrow[64 + lane * 3 + 0];
        float v1 = mrow[64 + lane * 3 + 1];
        float v2 = mrow[64 + lane * 3 + 2];
        float n00 = fabsf(ms0), n01 = fabsf(ms1);
        float n02 = sqrtf(v0 * v0 + v1 * v1 + v2 * v2);
        float s = n00 + n01 + n02;
        float s2 = n00 * n00 + n01 * n01 + n02 * n02;
#pragma unroll
        for (int o = 16; o; o >>= 1) {
            s  += __shfl_xor_sync(0xffffffffu, s, o);
            s2 += __shfl_xor_sync(0xffffffffu, s2, o);
        }
        float mu = s * (1.f / 96.f);
        float var = s2 * (1.f / 96.f) - mu * mu;
        float rstd = rsqrtf(var + 1e-5f);
        sX[w][lane]      = (n00 - mu) * rstd * ln_g[lane]      + ln_b[lane];
        sX[w][lane + 32] = (n01 - mu) * rstd * ln_g[lane + 32] + ln_b[lane + 32];
        sX[w][lane + 64] = (n02 - mu) * rstd * ln_g[lane + 64] + ln_b[lane + 64];
        __syncwarp();
#pragma unroll
        for (int t = 0; t < 3; t++) {
            int jp = lane + t * 32;
            float hs = b1[jp];
            for (int j = 0; j < 96; j++) hs += sX[w][j] * sW1[j * 96 + jp];
            sH[w][jp] = hs / (1.f + expf(-hs));
        }
        __syncwarp();
        float n0arr[3] = {n00, n01, n02};
        float f[3];
#pragma unroll
        for (int t = 0; t < 3; t++) {
            int jp = lane + t * 32;
            float gs = b2[jp];
            for (int j = 0; j < 96; j++) gs += sH[w][j] * W2[j * 96 + jp];
            float gg = gs / (1.f + expf(-gs));
            f[t] = gg / (n0arr[t] + 1e-6f);
        }
        out[n * 160 + lane]      = ms0 * f[0];
        out[n * 160 + 32 + lane] = ms1 * f[1];
        out[n * 160 + 64 + lane * 3 + 0] = v0 * f[2];
        out[n * 160 + 64 + lane * 3 + 1] = v1 * f[2];
        out[n * 160 + 64 + lane * 3 + 2] = v2 * f[2];
        __syncwarp();
    }
}

// ---------------- launch ----------------------------------------------------------------
extern "C" void kernel_launch(void* const* d_in, const int* in_sizes, int n_in,
                              void* d_out, int out_size) {
    const float* pseduo_x = (const float*)d_in[0];
    const float* rbf   = (const float*)d_in[1];
    const float* rsh   = (const float*)d_in[2];
    const int*   ei    = (const int*)d_in[3];
    const float* Wq_s  = (const float*)d_in[4];
    const float* Wq_v  = (const float*)d_in[5];
    const float* Wk_s  = (const float*)d_in[6];
    const float* Wk_v  = (const float*)d_in[7];
    const float* Wp_s  = (const float*)d_in[8];
    const float* Wp_v  = (const float*)d_in[9];
    const float* Wrbf  = (const float*)d_in[10];
    const float* Wv_s  = (const float*)d_in[11];
    const float* Wv_v  = (const float*)d_in[12];
    const float* Wm_s  = (const float*)d_in[13];
    const float* Wm_v  = (const float*)d_in[14];
    const float* ln_g  = (const float*)d_in[15];
    const float* ln_b  = (const float*)d_in[16];
    const float* W1    = (const float*)d_in[17];
    const float* b1    = (const float*)d_in[18];
    const float* W2    = (const float*)d_in[19];
    const float* b2    = (const float*)d_in[20];
    float* out = (float*)d_out;

    void* p;
    cudaGetSymbolAddress(&p, g_xT);  float* XT  = (float*)p;
    cudaGetSymbolAddress(&p, g_cnt); int*   CNT = (int*)p;

    cudaMemsetAsync(CNT, 0, NN * sizeof(int));
    k_prep<<<1585, 256>>>(Wq_s, Wq_v, Wk_s, Wk_v, Wp_s, Wp_v,
                          Wv_s, Wv_v, Wm_s, Wm_v, pseduo_x, XT, ei);

    k_gemmT_m<<<2817, 256>>>(XT);

    k_edge_qk<<<2304, 256>>>(rbf, rsh, ei, Wrbf, pseduo_x);

    k_attn_agg2<<<1024, 256>>>(pseduo_x, ei);

    k_projm<<<512, 256>>>();
    k_normgate<<<256, 256>>>(ln_g, ln_b, W1, b1, W2, b2, out);
}